// round 1
// baseline (speedup 1.0000x reference)
#include <cuda_runtime.h>
#include <math.h>

// Problem constants
#define Bq   2
#define Sq   2048
#define Dq   1024
#define Hq   16
#define DHq  64
#define Mq   (Bq*Sq)          // 4096 rows for the projection GEMMs
#define OUT_OFF  ((size_t)Bq*Sq*Dq)            // 4,194,304 floats (attention out)
// scores live at d_out + OUT_OFF, size B*H*S*S = 134,217,728 floats

// -------- scratch (no allocations allowed) --------
__device__ float g_q  [Mq*Dq];
__device__ float g_k  [Mq*Dq];
__device__ float g_v  [Mq*Dq];
__device__ float g_ctx[Mq*Dq];
__device__ float g_y  [Mq*Dq];

#define TS 64
#define KT 16

// ============================================================
// Projection GEMM: C[m,n] = sum_k A[m,k]*W[n,k] + bias[n] (+resid[m,n])
// A: [Mq,1024] row-major, W: [1024,1024] row-major (torch Linear weight)
// ============================================================
__global__ void proj_kernel(const float* __restrict__ A,
                            const float* __restrict__ W,
                            const float* __restrict__ bias,
                            const float* __restrict__ resid,
                            float* __restrict__ C)
{
    __shared__ float As[KT][TS + 1];
    __shared__ float Bs[KT][TS + 1];

    const int bm = blockIdx.y * TS;
    const int bn = blockIdx.x * TS;
    const int tid = threadIdx.x;
    const int tx = tid & 15;
    const int ty = tid >> 4;
    const int lk = tid & 15;   // k within k-tile
    const int lr = tid >> 4;   // row group base

    float acc[4][4] = {};

    for (int k0 = 0; k0 < 1024; k0 += KT) {
#pragma unroll
        for (int i = 0; i < 4; i++) {
            As[lk][lr + i*16] = A[(size_t)(bm + lr + i*16) * 1024 + k0 + lk];
            Bs[lk][lr + i*16] = W[(size_t)(bn + lr + i*16) * 1024 + k0 + lk];
        }
        __syncthreads();
#pragma unroll
        for (int kk = 0; kk < KT; kk++) {
            float a[4], b[4];
#pragma unroll
            for (int i = 0; i < 4; i++) a[i] = As[kk][ty*4 + i];
#pragma unroll
            for (int j = 0; j < 4; j++) b[j] = Bs[kk][tx*4 + j];
#pragma unroll
            for (int i = 0; i < 4; i++)
#pragma unroll
                for (int j = 0; j < 4; j++)
                    acc[i][j] = fmaf(a[i], b[j], acc[i][j]);
        }
        __syncthreads();
    }

#pragma unroll
    for (int i = 0; i < 4; i++) {
        const int m = bm + ty*4 + i;
        const int n = bn + tx*4;
        float4 r;
        r.x = acc[i][0] + bias[n+0];
        r.y = acc[i][1] + bias[n+1];
        r.z = acc[i][2] + bias[n+2];
        r.w = acc[i][3] + bias[n+3];
        if (resid) {
            const float4 q = *reinterpret_cast<const float4*>(&resid[(size_t)m*1024 + n]);
            r.x += q.x; r.y += q.y; r.z += q.z; r.w += q.w;
        }
        *reinterpret_cast<float4*>(&C[(size_t)m*1024 + n]) = r;
    }
}

// ============================================================
// Scores: per (b,h), C[q,k] = (q_row . k_row) / 8, written into d_out scores.
// q/k head slices: stride 1024, head offset h*64, K-dim = 64.
// ============================================================
__global__ void scores_kernel(float* __restrict__ scores)
{
    const int bh = blockIdx.z;
    const int b  = bh >> 4;
    const int h  = bh & 15;
    const float* A  = g_q + (size_t)b*Sq*Dq + h*DHq;
    const float* Bm = g_k + (size_t)b*Sq*Dq + h*DHq;
    float* C = scores + (size_t)bh * Sq * Sq;

    __shared__ float As[KT][TS + 1];
    __shared__ float Bs[KT][TS + 1];

    const int bm = blockIdx.y * TS;
    const int bn = blockIdx.x * TS;
    const int tid = threadIdx.x;
    const int tx = tid & 15;
    const int ty = tid >> 4;
    const int lk = tid & 15;
    const int lr = tid >> 4;

    float acc[4][4] = {};

    for (int k0 = 0; k0 < DHq; k0 += KT) {
#pragma unroll
        for (int i = 0; i < 4; i++) {
            As[lk][lr + i*16] = A [(size_t)(bm + lr + i*16) * 1024 + k0 + lk];
            Bs[lk][lr + i*16] = Bm[(size_t)(bn + lr + i*16) * 1024 + k0 + lk];
        }
        __syncthreads();
#pragma unroll
        for (int kk = 0; kk < KT; kk++) {
            float a[4], bb[4];
#pragma unroll
            for (int i = 0; i < 4; i++) a[i]  = As[kk][ty*4 + i];
#pragma unroll
            for (int j = 0; j < 4; j++) bb[j] = Bs[kk][tx*4 + j];
#pragma unroll
            for (int i = 0; i < 4; i++)
#pragma unroll
                for (int j = 0; j < 4; j++)
                    acc[i][j] = fmaf(a[i], bb[j], acc[i][j]);
        }
        __syncthreads();
    }

#pragma unroll
    for (int i = 0; i < 4; i++) {
        const int m = bm + ty*4 + i;
        const int n = bn + tx*4;
        float4 r;
        r.x = acc[i][0] * 0.125f;
        r.y = acc[i][1] * 0.125f;
        r.z = acc[i][2] * 0.125f;
        r.w = acc[i][3] * 0.125f;
        *reinterpret_cast<float4*>(&C[(size_t)m*Sq + n]) = r;
    }
}

// ============================================================
// In-place row softmax over the scores region. One block per row (2048 elems).
// ============================================================
__global__ void softmax_kernel(float* __restrict__ scores)
{
    const size_t row = blockIdx.x;
    float* p = scores + row * (size_t)Sq;
    const int tid = threadIdx.x;

    __shared__ float sm[8];

    float v[8];
    float lmax = -INFINITY;
#pragma unroll
    for (int t = 0; t < 8; t++) {
        v[t] = p[tid + t*256];
        lmax = fmaxf(lmax, v[t]);
    }
#pragma unroll
    for (int o = 16; o > 0; o >>= 1)
        lmax = fmaxf(lmax, __shfl_xor_sync(0xffffffffu, lmax, o));
    if ((tid & 31) == 0) sm[tid >> 5] = lmax;
    __syncthreads();
    float rmax = sm[0];
#pragma unroll
    for (int w = 1; w < 8; w++) rmax = fmaxf(rmax, sm[w]);
    __syncthreads();

    float lsum = 0.f;
#pragma unroll
    for (int t = 0; t < 8; t++) {
        v[t] = expf(v[t] - rmax);
        lsum += v[t];
    }
#pragma unroll
    for (int o = 16; o > 0; o >>= 1)
        lsum += __shfl_xor_sync(0xffffffffu, lsum, o);
    if ((tid & 31) == 0) sm[tid >> 5] = lsum;
    __syncthreads();
    float rsum = 0.f;
#pragma unroll
    for (int w = 0; w < 8; w++) rsum += sm[w];
    const float inv = 1.0f / rsum;

#pragma unroll
    for (int t = 0; t < 8; t++)
        p[tid + t*256] = v[t] * inv;
}

// ============================================================
// PV: per (b,h), ctx[q, h*64+d] = sum_k P[q,k] * V[k, h*64+d]
// One block = 64 queries x full Dh=64. K loop over 2048.
// ============================================================
__global__ void av_kernel(const float* __restrict__ scores)
{
    const int bh = blockIdx.z;
    const int b  = bh >> 4;
    const int h  = bh & 15;
    const float* P = scores + (size_t)bh * Sq * Sq;
    const float* V = g_v   + (size_t)b*Sq*Dq + h*DHq;
    float* C       = g_ctx + (size_t)b*Sq*Dq + h*DHq;

    __shared__ float As[KT][TS + 1];   // P tile, k-major
    __shared__ float Bs[KT][TS + 1];   // V tile, k-major (natural)

    const int bm = blockIdx.y * TS;    // query base
    const int tid = threadIdx.x;
    const int tx = tid & 15;
    const int ty = tid >> 4;

    const int lk = tid & 15;           // for P loads
    const int lr = tid >> 4;
    const int vk = tid >> 4;           // for V loads: k row
    const int vd = tid & 15;           // d group (x4)

    float acc[4][4] = {};

    for (int k0 = 0; k0 < Sq; k0 += KT) {
#pragma unroll
        for (int i = 0; i < 4; i++)
            As[lk][lr + i*16] = P[(size_t)(bm + lr + i*16) * Sq + k0 + lk];
        {
            const float4 vv = *reinterpret_cast<const float4*>(&V[(size_t)(k0 + vk) * 1024 + vd*4]);
            Bs[vk][vd*4 + 0] = vv.x;
            Bs[vk][vd*4 + 1] = vv.y;
            Bs[vk][vd*4 + 2] = vv.z;
            Bs[vk][vd*4 + 3] = vv.w;
        }
        __syncthreads();
#pragma unroll
        for (int kk = 0; kk < KT; kk++) {
            float a[4], bb[4];
#pragma unroll
            for (int i = 0; i < 4; i++) a[i]  = As[kk][ty*4 + i];
#pragma unroll
            for (int j = 0; j < 4; j++) bb[j] = Bs[kk][tx*4 + j];
#pragma unroll
            for (int i = 0; i < 4; i++)
#pragma unroll
                for (int j = 0; j < 4; j++)
                    acc[i][j] = fmaf(a[i], bb[j], acc[i][j]);
        }
        __syncthreads();
    }

#pragma unroll
    for (int i = 0; i < 4; i++) {
        const int m = bm + ty*4 + i;
        const int n = tx*4;
        float4 r = make_float4(acc[i][0], acc[i][1], acc[i][2], acc[i][3]);
        *reinterpret_cast<float4*>(&C[(size_t)m*1024 + n]) = r;
    }
}

// ============================================================
// LayerNorm per row of g_y -> d_out (first region)
// ============================================================
__global__ void ln_kernel(const float* __restrict__ gamma,
                          const float* __restrict__ beta,
                          float* __restrict__ out)
{
    const size_t row = blockIdx.x;
    const float* y = g_y + row * (size_t)Dq;
    float* o = out + row * (size_t)Dq;
    const int tid = threadIdx.x;

    __shared__ float sm[8], sm2[8];

    float v[4];
    float s = 0.f, s2 = 0.f;
#pragma unroll
    for (int t = 0; t < 4; t++) {
        v[t] = y[tid + t*256];
        s  += v[t];
        s2 += v[t]*v[t];
    }
#pragma unroll
    for (int o2 = 16; o2 > 0; o2 >>= 1) {
        s  += __shfl_xor_sync(0xffffffffu, s,  o2);
        s2 += __shfl_xor_sync(0xffffffffu, s2, o2);
    }
    if ((tid & 31) == 0) { sm[tid>>5] = s; sm2[tid>>5] = s2; }
    __syncthreads();
    float ts = 0.f, ts2 = 0.f;
#pragma unroll
    for (int w = 0; w < 8; w++) { ts += sm[w]; ts2 += sm2[w]; }
    const float mean = ts * (1.0f/Dq);
    const float var  = ts2 * (1.0f/Dq) - mean*mean;
    const float rstd = rsqrtf(var + 1e-6f);

#pragma unroll
    for (int t = 0; t < 4; t++) {
        const int c = tid + t*256;
        o[c] = (v[t] - mean) * rstd * gamma[c] + beta[c];
    }
}

// ============================================================
extern "C" void kernel_launch(void* const* d_in, const int* in_sizes, int n_in,
                              void* d_out, int out_size)
{
    const float* Q     = (const float*)d_in[0];
    const float* K     = (const float*)d_in[1];
    const float* V     = (const float*)d_in[2];
    const float* Wq    = (const float*)d_in[3];
    const float* bq    = (const float*)d_in[4];
    const float* Wk    = (const float*)d_in[5];
    const float* bk    = (const float*)d_in[6];
    const float* Wv    = (const float*)d_in[7];
    const float* bv    = (const float*)d_in[8];
    const float* Wo    = (const float*)d_in[9];
    const float* bo    = (const float*)d_in[10];
    const float* gamma = (const float*)d_in[11];
    const float* beta  = (const float*)d_in[12];

    float* out    = (float*)d_out;
    float* scores = out + OUT_OFF;

    float *gq, *gk, *gv, *gctx, *gy;
    cudaGetSymbolAddress((void**)&gq,   g_q);
    cudaGetSymbolAddress((void**)&gk,   g_k);
    cudaGetSymbolAddress((void**)&gv,   g_v);
    cudaGetSymbolAddress((void**)&gctx, g_ctx);
    cudaGetSymbolAddress((void**)&gy,   g_y);

    dim3 blk(256);

    // QKV projections: [4096,1024] x [1024,1024]^T
    dim3 gProj(Dq/TS, Mq/TS);                 // (16, 64)
    proj_kernel<<<gProj, blk>>>(Q, Wq, bq, nullptr, gq);
    proj_kernel<<<gProj, blk>>>(K, Wk, bk, nullptr, gk);
    proj_kernel<<<gProj, blk>>>(V, Wv, bv, nullptr, gv);

    // logits -> scores region
    dim3 gSc(Sq/TS, Sq/TS, Bq*Hq);            // (32, 32, 32)
    scores_kernel<<<gSc, blk>>>(scores);

    // softmax rows
    softmax_kernel<<<(unsigned)((size_t)Bq*Hq*Sq), blk>>>(scores);

    // PV
    dim3 gAv(1, Sq/TS, Bq*Hq);                // (1, 32, 32)
    av_kernel<<<gAv, blk>>>(scores);

    // O projection + bias + residual -> g_y
    proj_kernel<<<gProj, blk>>>(gctx, Wo, bo, Q, gy);

    // LayerNorm -> out region
    ln_kernel<<<(unsigned)Mq, blk>>>(gamma, beta, out);
}

// round 2
// speedup vs baseline: 1.3170x; 1.3170x over previous
#include <cuda_runtime.h>
#include <math.h>

// Problem constants
#define Bq   2
#define Sq   2048
#define Dq   1024
#define Hq   16
#define DHq  64
#define Mq   (Bq*Sq)
#define OUT_OFF  ((size_t)Bq*Sq*Dq)

// -------- scratch (no allocations allowed) --------
__device__ float g_q  [Mq*Dq];
__device__ float g_k  [Mq*Dq];
__device__ float g_v  [Mq*Dq];
__device__ float g_ctx[Mq*Dq];
__device__ float g_y  [Mq*Dq];

// ============================================================
// Projection GEMM: C[m,n] = sum_k A[m,k]*W[n,k] + bias[n] (+resid)
// 128x128 block tile, 256 threads, 8x8 per thread, BK=16.
// ============================================================
__global__ void proj_kernel(const float* __restrict__ A,
                            const float* __restrict__ W,
                            const float* __restrict__ bias,
                            const float* __restrict__ resid,
                            float* __restrict__ C)
{
    __shared__ float As[16][128];
    __shared__ float Bs[16][128];

    const int tid = threadIdx.x;
    const int bm = blockIdx.y * 128;
    const int bn = blockIdx.x * 128;
    const int tx = tid & 15;          // col group (8 cols)
    const int ty = tid >> 4;          // row group (8 rows)
    const int lr = tid & 127;         // load row
    const int lg = tid >> 7;          // 0..1

    float acc[8][8] = {};

    for (int k0 = 0; k0 < 1024; k0 += 16) {
#pragma unroll
        for (int t = 0; t < 2; t++) {
            const int g = lg + t*2;   // k group of 4
            float4 va = *reinterpret_cast<const float4*>(&A[(size_t)(bm + lr)*1024 + k0 + g*4]);
            As[g*4+0][lr] = va.x; As[g*4+1][lr] = va.y;
            As[g*4+2][lr] = va.z; As[g*4+3][lr] = va.w;
            float4 vb = *reinterpret_cast<const float4*>(&W[(size_t)(bn + lr)*1024 + k0 + g*4]);
            Bs[g*4+0][lr] = vb.x; Bs[g*4+1][lr] = vb.y;
            Bs[g*4+2][lr] = vb.z; Bs[g*4+3][lr] = vb.w;
        }
        __syncthreads();
#pragma unroll
        for (int kk = 0; kk < 16; kk++) {
            float a[8], b[8];
            *reinterpret_cast<float4*>(&a[0]) = *reinterpret_cast<float4*>(&As[kk][ty*8]);
            *reinterpret_cast<float4*>(&a[4]) = *reinterpret_cast<float4*>(&As[kk][ty*8+4]);
            *reinterpret_cast<float4*>(&b[0]) = *reinterpret_cast<float4*>(&Bs[kk][tx*8]);
            *reinterpret_cast<float4*>(&b[4]) = *reinterpret_cast<float4*>(&Bs[kk][tx*8+4]);
#pragma unroll
            for (int i = 0; i < 8; i++)
#pragma unroll
                for (int j = 0; j < 8; j++)
                    acc[i][j] = fmaf(a[i], b[j], acc[i][j]);
        }
        __syncthreads();
    }

#pragma unroll
    for (int i = 0; i < 8; i++) {
        const int m = bm + ty*8 + i;
#pragma unroll
        for (int jj = 0; jj < 2; jj++) {
            const int n = bn + tx*8 + jj*4;
            float4 r;
            r.x = acc[i][jj*4+0] + bias[n+0];
            r.y = acc[i][jj*4+1] + bias[n+1];
            r.z = acc[i][jj*4+2] + bias[n+2];
            r.w = acc[i][jj*4+3] + bias[n+3];
            if (resid) {
                const float4 q = *reinterpret_cast<const float4*>(&resid[(size_t)m*1024 + n]);
                r.x += q.x; r.y += q.y; r.z += q.z; r.w += q.w;
            }
            *reinterpret_cast<float4*>(&C[(size_t)m*1024 + n]) = r;
        }
    }
}

// ============================================================
// Scores: per (b,h), C[q,k] = (q . k)/8. 128x128 tile, K=64.
// ============================================================
__global__ void scores_kernel(float* __restrict__ scores)
{
    const int bh = blockIdx.z;
    const int b  = bh >> 4;
    const int h  = bh & 15;
    const float* A  = g_q + (size_t)b*Sq*Dq + h*DHq;
    const float* Bm = g_k + (size_t)b*Sq*Dq + h*DHq;
    float* C = scores + (size_t)bh * Sq * Sq;

    __shared__ float As[16][128];
    __shared__ float Bs[16][128];

    const int tid = threadIdx.x;
    const int bm = blockIdx.y * 128;
    const int bn = blockIdx.x * 128;
    const int tx = tid & 15;
    const int ty = tid >> 4;
    const int lr = tid & 127;
    const int lg = tid >> 7;

    float acc[8][8] = {};

    for (int k0 = 0; k0 < DHq; k0 += 16) {
#pragma unroll
        for (int t = 0; t < 2; t++) {
            const int g = lg + t*2;
            float4 va = *reinterpret_cast<const float4*>(&A[(size_t)(bm + lr)*1024 + k0 + g*4]);
            As[g*4+0][lr] = va.x; As[g*4+1][lr] = va.y;
            As[g*4+2][lr] = va.z; As[g*4+3][lr] = va.w;
            float4 vb = *reinterpret_cast<const float4*>(&Bm[(size_t)(bn + lr)*1024 + k0 + g*4]);
            Bs[g*4+0][lr] = vb.x; Bs[g*4+1][lr] = vb.y;
            Bs[g*4+2][lr] = vb.z; Bs[g*4+3][lr] = vb.w;
        }
        __syncthreads();
#pragma unroll
        for (int kk = 0; kk < 16; kk++) {
            float a[8], b2[8];
            *reinterpret_cast<float4*>(&a[0])  = *reinterpret_cast<float4*>(&As[kk][ty*8]);
            *reinterpret_cast<float4*>(&a[4])  = *reinterpret_cast<float4*>(&As[kk][ty*8+4]);
            *reinterpret_cast<float4*>(&b2[0]) = *reinterpret_cast<float4*>(&Bs[kk][tx*8]);
            *reinterpret_cast<float4*>(&b2[4]) = *reinterpret_cast<float4*>(&Bs[kk][tx*8+4]);
#pragma unroll
            for (int i = 0; i < 8; i++)
#pragma unroll
                for (int j = 0; j < 8; j++)
                    acc[i][j] = fmaf(a[i], b2[j], acc[i][j]);
        }
        __syncthreads();
    }

#pragma unroll
    for (int i = 0; i < 8; i++) {
        const int m = bm + ty*8 + i;
#pragma unroll
        for (int jj = 0; jj < 2; jj++) {
            const int n = bn + tx*8 + jj*4;
            float4 r;
            r.x = acc[i][jj*4+0] * 0.125f;
            r.y = acc[i][jj*4+1] * 0.125f;
            r.z = acc[i][jj*4+2] * 0.125f;
            r.w = acc[i][jj*4+3] * 0.125f;
            *reinterpret_cast<float4*>(&C[(size_t)m*Sq + n]) = r;
        }
    }
}

// ============================================================
// In-place row softmax (2048 per row), float4.
// ============================================================
__global__ void softmax_kernel(float* __restrict__ scores)
{
    const size_t row = blockIdx.x;
    float4* p = reinterpret_cast<float4*>(scores + row * (size_t)Sq);
    const int tid = threadIdx.x;

    __shared__ float sm[8];

    float4 v[2];
    float lmax = -INFINITY;
#pragma unroll
    for (int t = 0; t < 2; t++) {
        v[t] = p[tid + t*256];
        lmax = fmaxf(lmax, fmaxf(fmaxf(v[t].x, v[t].y), fmaxf(v[t].z, v[t].w)));
    }
#pragma unroll
    for (int o = 16; o > 0; o >>= 1)
        lmax = fmaxf(lmax, __shfl_xor_sync(0xffffffffu, lmax, o));
    if ((tid & 31) == 0) sm[tid >> 5] = lmax;
    __syncthreads();
    float rmax = sm[0];
#pragma unroll
    for (int w = 1; w < 8; w++) rmax = fmaxf(rmax, sm[w]);
    __syncthreads();

    float lsum = 0.f;
#pragma unroll
    for (int t = 0; t < 2; t++) {
        v[t].x = expf(v[t].x - rmax); v[t].y = expf(v[t].y - rmax);
        v[t].z = expf(v[t].z - rmax); v[t].w = expf(v[t].w - rmax);
        lsum += v[t].x + v[t].y + v[t].z + v[t].w;
    }
#pragma unroll
    for (int o = 16; o > 0; o >>= 1)
        lsum += __shfl_xor_sync(0xffffffffu, lsum, o);
    if ((tid & 31) == 0) sm[tid >> 5] = lsum;
    __syncthreads();
    float rsum = 0.f;
#pragma unroll
    for (int w = 0; w < 8; w++) rsum += sm[w];
    const float inv = 1.0f / rsum;

#pragma unroll
    for (int t = 0; t < 2; t++) {
        v[t].x *= inv; v[t].y *= inv; v[t].z *= inv; v[t].w *= inv;
        p[tid + t*256] = v[t];
    }
}

// ============================================================
// PV: ctx[q, h*64+d] = sum_k P[q,k] * V[k, h*64+d]
// 128x64 tile, 256 threads, 8x4 per thread, BK=16, K=2048.
// ============================================================
__global__ void av_kernel(const float* __restrict__ scores)
{
    const int bh = blockIdx.z;
    const int b  = bh >> 4;
    const int h  = bh & 15;
    const float* P = scores + (size_t)bh * Sq * Sq;
    const float* V = g_v   + (size_t)b*Sq*Dq + h*DHq;
    float* C       = g_ctx + (size_t)b*Sq*Dq + h*DHq;

    __shared__ float Ps[16][128];
    __shared__ float Vs[16][64];

    const int tid = threadIdx.x;
    const int bm = blockIdx.y * 128;
    const int tx = tid & 15;          // 4 cols each
    const int ty = tid >> 4;          // 8 rows each
    const int lr = tid & 127;
    const int lg = tid >> 7;
    const int vk = tid >> 4;          // V: k row 0..15
    const int vd = tid & 15;          // V: col group of 4

    float acc[8][4] = {};

    for (int k0 = 0; k0 < Sq; k0 += 16) {
#pragma unroll
        for (int t = 0; t < 2; t++) {
            const int g = lg + t*2;
            float4 pv = *reinterpret_cast<const float4*>(&P[(size_t)(bm + lr)*Sq + k0 + g*4]);
            Ps[g*4+0][lr] = pv.x; Ps[g*4+1][lr] = pv.y;
            Ps[g*4+2][lr] = pv.z; Ps[g*4+3][lr] = pv.w;
        }
        {
            const float4 vv = *reinterpret_cast<const float4*>(&V[(size_t)(k0 + vk)*1024 + vd*4]);
            Vs[vk][vd*4+0] = vv.x; Vs[vk][vd*4+1] = vv.y;
            Vs[vk][vd*4+2] = vv.z; Vs[vk][vd*4+3] = vv.w;
        }
        __syncthreads();
#pragma unroll
        for (int kk = 0; kk < 16; kk++) {
            float a[8], b2[4];
            *reinterpret_cast<float4*>(&a[0])  = *reinterpret_cast<float4*>(&Ps[kk][ty*8]);
            *reinterpret_cast<float4*>(&a[4])  = *reinterpret_cast<float4*>(&Ps[kk][ty*8+4]);
            *reinterpret_cast<float4*>(&b2[0]) = *reinterpret_cast<float4*>(&Vs[kk][tx*4]);
#pragma unroll
            for (int i = 0; i < 8; i++)
#pragma unroll
                for (int j = 0; j < 4; j++)
                    acc[i][j] = fmaf(a[i], b2[j], acc[i][j]);
        }
        __syncthreads();
    }

#pragma unroll
    for (int i = 0; i < 8; i++) {
        const int m = bm + ty*8 + i;
        float4 r = make_float4(acc[i][0], acc[i][1], acc[i][2], acc[i][3]);
        *reinterpret_cast<float4*>(&C[(size_t)m*1024 + tx*4]) = r;
    }
}

// ============================================================
// LayerNorm per row of g_y -> d_out
// ============================================================
__global__ void ln_kernel(const float* __restrict__ gamma,
                          const float* __restrict__ beta,
                          float* __restrict__ out)
{
    const size_t row = blockIdx.x;
    const float4* y = reinterpret_cast<const float4*>(g_y + row * (size_t)Dq);
    float4* o = reinterpret_cast<float4*>(out + row * (size_t)Dq);
    const int tid = threadIdx.x;

    __shared__ float sm[8], sm2[8];

    float4 v = y[tid];
    float s  = v.x + v.y + v.z + v.w;
    float s2 = v.x*v.x + v.y*v.y + v.z*v.z + v.w*v.w;
#pragma unroll
    for (int o2 = 16; o2 > 0; o2 >>= 1) {
        s  += __shfl_xor_sync(0xffffffffu, s,  o2);
        s2 += __shfl_xor_sync(0xffffffffu, s2, o2);
    }
    if ((tid & 31) == 0) { sm[tid>>5] = s; sm2[tid>>5] = s2; }
    __syncthreads();
    float ts = 0.f, ts2 = 0.f;
#pragma unroll
    for (int w = 0; w < 8; w++) { ts += sm[w]; ts2 += sm2[w]; }
    const float mean = ts * (1.0f/Dq);
    const float var  = ts2 * (1.0f/Dq) - mean*mean;
    const float rstd = rsqrtf(var + 1e-6f);

    const float4 g = reinterpret_cast<const float4*>(gamma)[tid];
    const float4 bb = reinterpret_cast<const float4*>(beta)[tid];
    float4 r;
    r.x = (v.x - mean) * rstd * g.x + bb.x;
    r.y = (v.y - mean) * rstd * g.y + bb.y;
    r.z = (v.z - mean) * rstd * g.z + bb.z;
    r.w = (v.w - mean) * rstd * g.w + bb.w;
    o[tid] = r;
}

// ============================================================
extern "C" void kernel_launch(void* const* d_in, const int* in_sizes, int n_in,
                              void* d_out, int out_size)
{
    const float* Q     = (const float*)d_in[0];
    const float* K     = (const float*)d_in[1];
    const float* V     = (const float*)d_in[2];
    const float* Wq    = (const float*)d_in[3];
    const float* bq    = (const float*)d_in[4];
    const float* Wk    = (const float*)d_in[5];
    const float* bk    = (const float*)d_in[6];
    const float* Wv    = (const float*)d_in[7];
    const float* bv    = (const float*)d_in[8];
    const float* Wo    = (const float*)d_in[9];
    const float* bo    = (const float*)d_in[10];
    const float* gamma = (const float*)d_in[11];
    const float* beta  = (const float*)d_in[12];

    float* out    = (float*)d_out;
    float* scores = out + OUT_OFF;

    float *gq, *gk, *gv, *gctx, *gy;
    cudaGetSymbolAddress((void**)&gq,   g_q);
    cudaGetSymbolAddress((void**)&gk,   g_k);
    cudaGetSymbolAddress((void**)&gv,   g_v);
    cudaGetSymbolAddress((void**)&gctx, g_ctx);
    cudaGetSymbolAddress((void**)&gy,   g_y);

    dim3 blk(256);

    // QKV projections: [4096,1024] x [1024,1024]^T
    dim3 gProj(Dq/128, Mq/128);               // (8, 32)
    proj_kernel<<<gProj, blk>>>(Q, Wq, bq, nullptr, gq);
    proj_kernel<<<gProj, blk>>>(K, Wk, bk, nullptr, gk);
    proj_kernel<<<gProj, blk>>>(V, Wv, bv, nullptr, gv);

    // logits -> scores region
    dim3 gSc(Sq/128, Sq/128, Bq*Hq);          // (16, 16, 32)
    scores_kernel<<<gSc, blk>>>(scores);

    // softmax rows
    softmax_kernel<<<(unsigned)((size_t)Bq*Hq*Sq), blk>>>(scores);

    // PV
    dim3 gAv(1, Sq/128, Bq*Hq);               // (1, 16, 32)
    av_kernel<<<gAv, blk>>>(scores);

    // O projection + bias + residual -> g_y
    proj_kernel<<<gProj, blk>>>(gctx, Wo, bo, Q, gy);

    // LayerNorm -> out region
    ln_kernel<<<(unsigned)Mq, blk>>>(gamma, beta, out);
}

// round 3
// speedup vs baseline: 1.7487x; 1.3278x over previous
#include <cuda_runtime.h>
#include <math.h>
#include <stdint.h>

// Problem constants
#define Bq   2
#define Sq   2048
#define Dq   1024
#define Hq   16
#define DHq  64
#define Mq   (Bq*Sq)
#define OUT_OFF  ((size_t)Bq*Sq*Dq)

// -------- scratch (no allocations allowed) --------
__device__ float g_q  [Mq*Dq];
__device__ float g_k  [Mq*Dq];
__device__ float g_v  [Mq*Dq];
__device__ float g_ctx[Mq*Dq];
__device__ float g_y  [Mq*Dq];

#define PAD 20   // 128x16 tile padded to 20 cols -> conflict-free fragment LDS

// ---------------- tf32 helpers ----------------
__device__ __forceinline__ uint32_t f2tf(float x) {
    uint32_t u; asm("cvt.rna.tf32.f32 %0, %1;" : "=r"(u) : "f"(x)); return u;
}
__device__ __forceinline__ void split_tf32(float a, float& hi, float& lo) {
    uint32_t uh = f2tf(a);
    hi = __uint_as_float(uh);
    lo = __uint_as_float(f2tf(a - hi));
}
__device__ __forceinline__ void mma_tf32(float* c,
    uint32_t a0, uint32_t a1, uint32_t a2, uint32_t a3,
    uint32_t b0, uint32_t b1)
{
    asm volatile(
        "mma.sync.aligned.m16n8k8.row.col.f32.tf32.tf32.f32 "
        "{%0,%1,%2,%3}, {%4,%5,%6,%7}, {%8,%9}, {%0,%1,%2,%3};"
        : "+f"(c[0]), "+f"(c[1]), "+f"(c[2]), "+f"(c[3])
        : "r"(a0), "r"(a1), "r"(a2), "r"(a3), "r"(b0), "r"(b1));
}

// ============================================================
// Projection GEMM (NT): C[m,n] = sum_k A[m,k]*W[n,k] + bias (+resid)
// 128x128 block, 8 warps (64x32 warp tile), BK=16, 3xTF32 mma.
// ============================================================
__global__ __launch_bounds__(256,2) void proj_kernel(
    const float* __restrict__ A, const float* __restrict__ W,
    const float* __restrict__ bias, const float* __restrict__ resid,
    float* __restrict__ C)
{
    __shared__ float Ah[128][PAD], Al[128][PAD];
    __shared__ float Bh[128][PAD], Bl[128][PAD];

    const int tid  = threadIdx.x;
    const int warp = tid >> 5, lane = tid & 31;
    const int wm = (warp >> 2) * 64;
    const int wn = (warp &  3) * 32;
    const int bm = blockIdx.y * 128, bn = blockIdx.x * 128;
    const int g  = lane >> 2, tg = lane & 3;

    float acc[4][4][4] = {};

    for (int k0 = 0; k0 < 1024; k0 += 16) {
#pragma unroll
        for (int t = 0; t < 2; t++) {
            const int linear = tid + t*256;
            const int row = linear >> 2, c4 = (linear & 3) * 4;
            float4 va = *reinterpret_cast<const float4*>(&A[(size_t)(bm+row)*1024 + k0 + c4]);
            float4 h4, l4;
            split_tf32(va.x, h4.x, l4.x); split_tf32(va.y, h4.y, l4.y);
            split_tf32(va.z, h4.z, l4.z); split_tf32(va.w, h4.w, l4.w);
            *reinterpret_cast<float4*>(&Ah[row][c4]) = h4;
            *reinterpret_cast<float4*>(&Al[row][c4]) = l4;
            float4 vb = *reinterpret_cast<const float4*>(&W[(size_t)(bn+row)*1024 + k0 + c4]);
            split_tf32(vb.x, h4.x, l4.x); split_tf32(vb.y, h4.y, l4.y);
            split_tf32(vb.z, h4.z, l4.z); split_tf32(vb.w, h4.w, l4.w);
            *reinterpret_cast<float4*>(&Bh[row][c4]) = h4;
            *reinterpret_cast<float4*>(&Bl[row][c4]) = l4;
        }
        __syncthreads();
#pragma unroll
        for (int ks = 0; ks < 16; ks += 8) {
            uint32_t bh0[4], bh1[4], bl0[4], bl1[4];
#pragma unroll
            for (int ni = 0; ni < 4; ni++) {
                const int n = wn + ni*8 + g;
                bh0[ni] = __float_as_uint(Bh[n][ks+tg]);
                bh1[ni] = __float_as_uint(Bh[n][ks+tg+4]);
                bl0[ni] = __float_as_uint(Bl[n][ks+tg]);
                bl1[ni] = __float_as_uint(Bl[n][ks+tg+4]);
            }
#pragma unroll
            for (int mi = 0; mi < 4; mi++) {
                const int r0 = wm + mi*16 + g;
                uint32_t ah0 = __float_as_uint(Ah[r0  ][ks+tg]);
                uint32_t ah1 = __float_as_uint(Ah[r0+8][ks+tg]);
                uint32_t ah2 = __float_as_uint(Ah[r0  ][ks+tg+4]);
                uint32_t ah3 = __float_as_uint(Ah[r0+8][ks+tg+4]);
                uint32_t al0 = __float_as_uint(Al[r0  ][ks+tg]);
                uint32_t al1 = __float_as_uint(Al[r0+8][ks+tg]);
                uint32_t al2 = __float_as_uint(Al[r0  ][ks+tg+4]);
                uint32_t al3 = __float_as_uint(Al[r0+8][ks+tg+4]);
#pragma unroll
                for (int ni = 0; ni < 4; ni++) {
                    mma_tf32(acc[mi][ni], ah0,ah1,ah2,ah3, bh0[ni],bh1[ni]);
                    mma_tf32(acc[mi][ni], ah0,ah1,ah2,ah3, bl0[ni],bl1[ni]);
                    mma_tf32(acc[mi][ni], al0,al1,al2,al3, bh0[ni],bh1[ni]);
                }
            }
        }
        __syncthreads();
    }

#pragma unroll
    for (int mi = 0; mi < 4; mi++) {
#pragma unroll
        for (int ni = 0; ni < 4; ni++) {
            const int row0 = bm + wm + mi*16 + g;
            const int col  = bn + wn + ni*8 + tg*2;
            const float2 bv = *reinterpret_cast<const float2*>(&bias[col]);
            float2 r0 = make_float2(acc[mi][ni][0]+bv.x, acc[mi][ni][1]+bv.y);
            float2 r1 = make_float2(acc[mi][ni][2]+bv.x, acc[mi][ni][3]+bv.y);
            if (resid) {
                const float2 q0 = *reinterpret_cast<const float2*>(&resid[(size_t)row0*1024+col]);
                const float2 q1 = *reinterpret_cast<const float2*>(&resid[(size_t)(row0+8)*1024+col]);
                r0.x += q0.x; r0.y += q0.y; r1.x += q1.x; r1.y += q1.y;
            }
            *reinterpret_cast<float2*>(&C[(size_t)row0*1024+col])     = r0;
            *reinterpret_cast<float2*>(&C[(size_t)(row0+8)*1024+col]) = r1;
        }
    }
}

// ============================================================
// Scores (NT): per (b,h), P[q,kq] = (q . k)/8. K=64. 128x128 block.
// ============================================================
__global__ __launch_bounds__(256,2) void scores_kernel(float* __restrict__ scores)
{
    const int bh = blockIdx.z;
    const int b  = bh >> 4;
    const int h  = bh & 15;
    const float* A  = g_q + (size_t)b*Sq*Dq + h*DHq;
    const float* Bm = g_k + (size_t)b*Sq*Dq + h*DHq;
    float* C = scores + (size_t)bh * Sq * Sq;

    __shared__ float Ah[128][PAD], Al[128][PAD];
    __shared__ float Bh[128][PAD], Bl[128][PAD];

    const int tid  = threadIdx.x;
    const int warp = tid >> 5, lane = tid & 31;
    const int wm = (warp >> 2) * 64;
    const int wn = (warp &  3) * 32;
    const int bm = blockIdx.y * 128, bn = blockIdx.x * 128;
    const int g  = lane >> 2, tg = lane & 3;

    float acc[4][4][4] = {};

    for (int k0 = 0; k0 < DHq; k0 += 16) {
#pragma unroll
        for (int t = 0; t < 2; t++) {
            const int linear = tid + t*256;
            const int row = linear >> 2, c4 = (linear & 3) * 4;
            float4 va = *reinterpret_cast<const float4*>(&A[(size_t)(bm+row)*1024 + k0 + c4]);
            float4 h4, l4;
            split_tf32(va.x, h4.x, l4.x); split_tf32(va.y, h4.y, l4.y);
            split_tf32(va.z, h4.z, l4.z); split_tf32(va.w, h4.w, l4.w);
            *reinterpret_cast<float4*>(&Ah[row][c4]) = h4;
            *reinterpret_cast<float4*>(&Al[row][c4]) = l4;
            float4 vb = *reinterpret_cast<const float4*>(&Bm[(size_t)(bn+row)*1024 + k0 + c4]);
            split_tf32(vb.x, h4.x, l4.x); split_tf32(vb.y, h4.y, l4.y);
            split_tf32(vb.z, h4.z, l4.z); split_tf32(vb.w, h4.w, l4.w);
            *reinterpret_cast<float4*>(&Bh[row][c4]) = h4;
            *reinterpret_cast<float4*>(&Bl[row][c4]) = l4;
        }
        __syncthreads();
#pragma unroll
        for (int ks = 0; ks < 16; ks += 8) {
            uint32_t bh0[4], bh1[4], bl0[4], bl1[4];
#pragma unroll
            for (int ni = 0; ni < 4; ni++) {
                const int n = wn + ni*8 + g;
                bh0[ni] = __float_as_uint(Bh[n][ks+tg]);
                bh1[ni] = __float_as_uint(Bh[n][ks+tg+4]);
                bl0[ni] = __float_as_uint(Bl[n][ks+tg]);
                bl1[ni] = __float_as_uint(Bl[n][ks+tg+4]);
            }
#pragma unroll
            for (int mi = 0; mi < 4; mi++) {
                const int r0 = wm + mi*16 + g;
                uint32_t ah0 = __float_as_uint(Ah[r0  ][ks+tg]);
                uint32_t ah1 = __float_as_uint(Ah[r0+8][ks+tg]);
                uint32_t ah2 = __float_as_uint(Ah[r0  ][ks+tg+4]);
                uint32_t ah3 = __float_as_uint(Ah[r0+8][ks+tg+4]);
                uint32_t al0 = __float_as_uint(Al[r0  ][ks+tg]);
                uint32_t al1 = __float_as_uint(Al[r0+8][ks+tg]);
                uint32_t al2 = __float_as_uint(Al[r0  ][ks+tg+4]);
                uint32_t al3 = __float_as_uint(Al[r0+8][ks+tg+4]);
#pragma unroll
                for (int ni = 0; ni < 4; ni++) {
                    mma_tf32(acc[mi][ni], ah0,ah1,ah2,ah3, bh0[ni],bh1[ni]);
                    mma_tf32(acc[mi][ni], ah0,ah1,ah2,ah3, bl0[ni],bl1[ni]);
                    mma_tf32(acc[mi][ni], al0,al1,al2,al3, bh0[ni],bh1[ni]);
                }
            }
        }
        __syncthreads();
    }

#pragma unroll
    for (int mi = 0; mi < 4; mi++) {
#pragma unroll
        for (int ni = 0; ni < 4; ni++) {
            const int row0 = bm + wm + mi*16 + g;
            const int col  = bn + wn + ni*8 + tg*2;
            float2 r0 = make_float2(acc[mi][ni][0]*0.125f, acc[mi][ni][1]*0.125f);
            float2 r1 = make_float2(acc[mi][ni][2]*0.125f, acc[mi][ni][3]*0.125f);
            *reinterpret_cast<float2*>(&C[(size_t)row0*Sq+col])     = r0;
            *reinterpret_cast<float2*>(&C[(size_t)(row0+8)*Sq+col]) = r1;
        }
    }
}

// ============================================================
// In-place row softmax (2048 per row), float4.
// ============================================================
__global__ void softmax_kernel(float* __restrict__ scores)
{
    const size_t row = blockIdx.x;
    float4* p = reinterpret_cast<float4*>(scores + row * (size_t)Sq);
    const int tid = threadIdx.x;

    __shared__ float sm[8];

    float4 v[2];
    float lmax = -INFINITY;
#pragma unroll
    for (int t = 0; t < 2; t++) {
        v[t] = p[tid + t*256];
        lmax = fmaxf(lmax, fmaxf(fmaxf(v[t].x, v[t].y), fmaxf(v[t].z, v[t].w)));
    }
#pragma unroll
    for (int o = 16; o > 0; o >>= 1)
        lmax = fmaxf(lmax, __shfl_xor_sync(0xffffffffu, lmax, o));
    if ((tid & 31) == 0) sm[tid >> 5] = lmax;
    __syncthreads();
    float rmax = sm[0];
#pragma unroll
    for (int w = 1; w < 8; w++) rmax = fmaxf(rmax, sm[w]);
    __syncthreads();

    float lsum = 0.f;
#pragma unroll
    for (int t = 0; t < 2; t++) {
        v[t].x = expf(v[t].x - rmax); v[t].y = expf(v[t].y - rmax);
        v[t].z = expf(v[t].z - rmax); v[t].w = expf(v[t].w - rmax);
        lsum += v[t].x + v[t].y + v[t].z + v[t].w;
    }
#pragma unroll
    for (int o = 16; o > 0; o >>= 1)
        lsum += __shfl_xor_sync(0xffffffffu, lsum, o);
    if ((tid & 31) == 0) sm[tid >> 5] = lsum;
    __syncthreads();
    float rsum = 0.f;
#pragma unroll
    for (int w = 0; w < 8; w++) rsum += sm[w];
    const float inv = 1.0f / rsum;

#pragma unroll
    for (int t = 0; t < 2; t++) {
        v[t].x *= inv; v[t].y *= inv; v[t].z *= inv; v[t].w *= inv;
        p[tid + t*256] = v[t];
    }
}

// ============================================================
// PV (NN): ctx[q, h*64+d] = sum_k P[q,k]*V[k, h*64+d]
// 128x64 block, 8 warps (32x32 warp tile), BK=16, V transposed on load.
// ============================================================
__global__ __launch_bounds__(256,2) void av_kernel(const float* __restrict__ scores)
{
    const int bh = blockIdx.z;
    const int b  = bh >> 4;
    const int h  = bh & 15;
    const float* P = scores + (size_t)bh * Sq * Sq;
    const float* V = g_v   + (size_t)b*Sq*Dq + h*DHq;
    float* C       = g_ctx + (size_t)b*Sq*Dq + h*DHq;

    __shared__ float Ah[128][PAD], Al[128][PAD];
    __shared__ float Vh[64][PAD],  Vl[64][PAD];

    const int tid  = threadIdx.x;
    const int warp = tid >> 5, lane = tid & 31;
    const int wm = (warp >> 1) * 32;
    const int wn = (warp &  1) * 32;
    const int bm = blockIdx.y * 128;
    const int g  = lane >> 2, tg = lane & 3;

    float acc[2][4][4] = {};

    for (int k0 = 0; k0 < Sq; k0 += 16) {
        // P tile (128x16), row-major k-contiguous
#pragma unroll
        for (int t = 0; t < 2; t++) {
            const int linear = tid + t*256;
            const int row = linear >> 2, c4 = (linear & 3) * 4;
            float4 pv = *reinterpret_cast<const float4*>(&P[(size_t)(bm+row)*Sq + k0 + c4]);
            float4 h4, l4;
            split_tf32(pv.x, h4.x, l4.x); split_tf32(pv.y, h4.y, l4.y);
            split_tf32(pv.z, h4.z, l4.z); split_tf32(pv.w, h4.w, l4.w);
            *reinterpret_cast<float4*>(&Ah[row][c4]) = h4;
            *reinterpret_cast<float4*>(&Al[row][c4]) = l4;
        }
        // V tile (16k x 64n) -> transposed store Vh[n][k]
        {
            const int k = tid >> 4;
            const int n4 = (tid & 15) * 4;
            float4 vv = *reinterpret_cast<const float4*>(&V[(size_t)(k0+k)*1024 + n4]);
            float h, l;
            split_tf32(vv.x, h, l); Vh[n4+0][k] = h; Vl[n4+0][k] = l;
            split_tf32(vv.y, h, l); Vh[n4+1][k] = h; Vl[n4+1][k] = l;
            split_tf32(vv.z, h, l); Vh[n4+2][k] = h; Vl[n4+2][k] = l;
            split_tf32(vv.w, h, l); Vh[n4+3][k] = h; Vl[n4+3][k] = l;
        }
        __syncthreads();
#pragma unroll
        for (int ks = 0; ks < 16; ks += 8) {
            uint32_t bh0[4], bh1[4], bl0[4], bl1[4];
#pragma unroll
            for (int ni = 0; ni < 4; ni++) {
                const int n = wn + ni*8 + g;
                bh0[ni] = __float_as_uint(Vh[n][ks+tg]);
                bh1[ni] = __float_as_uint(Vh[n][ks+tg+4]);
                bl0[ni] = __float_as_uint(Vl[n][ks+tg]);
                bl1[ni] = __float_as_uint(Vl[n][ks+tg+4]);
            }
#pragma unroll
            for (int mi = 0; mi < 2; mi++) {
                const int r0 = wm + mi*16 + g;
                uint32_t ah0 = __float_as_uint(Ah[r0  ][ks+tg]);
                uint32_t ah1 = __float_as_uint(Ah[r0+8][ks+tg]);
                uint32_t ah2 = __float_as_uint(Ah[r0  ][ks+tg+4]);
                uint32_t ah3 = __float_as_uint(Ah[r0+8][ks+tg+4]);
                uint32_t al0 = __float_as_uint(Al[r0  ][ks+tg]);
                uint32_t al1 = __float_as_uint(Al[r0+8][ks+tg]);
                uint32_t al2 = __float_as_uint(Al[r0  ][ks+tg+4]);
                uint32_t al3 = __float_as_uint(Al[r0+8][ks+tg+4]);
#pragma unroll
                for (int ni = 0; ni < 4; ni++) {
                    mma_tf32(acc[mi][ni], ah0,ah1,ah2,ah3, bh0[ni],bh1[ni]);
                    mma_tf32(acc[mi][ni], ah0,ah1,ah2,ah3, bl0[ni],bl1[ni]);
                    mma_tf32(acc[mi][ni], al0,al1,al2,al3, bh0[ni],bh1[ni]);
                }
            }
        }
        __syncthreads();
    }

#pragma unroll
    for (int mi = 0; mi < 2; mi++) {
#pragma unroll
        for (int ni = 0; ni < 4; ni++) {
            const int row0 = bm + wm + mi*16 + g;
            const int col  = wn + ni*8 + tg*2;
            *reinterpret_cast<float2*>(&C[(size_t)row0*1024+col]) =
                make_float2(acc[mi][ni][0], acc[mi][ni][1]);
            *reinterpret_cast<float2*>(&C[(size_t)(row0+8)*1024+col]) =
                make_float2(acc[mi][ni][2], acc[mi][ni][3]);
        }
    }
}

// ============================================================
// LayerNorm per row of g_y -> d_out
// ============================================================
__global__ void ln_kernel(const float* __restrict__ gamma,
                          const float* __restrict__ beta,
                          float* __restrict__ out)
{
    const size_t row = blockIdx.x;
    const float4* y = reinterpret_cast<const float4*>(g_y + row * (size_t)Dq);
    float4* o = reinterpret_cast<float4*>(out + row * (size_t)Dq);
    const int tid = threadIdx.x;

    __shared__ float sm[8], sm2[8];

    float4 v = y[tid];
    float s  = v.x + v.y + v.z + v.w;
    float s2 = v.x*v.x + v.y*v.y + v.z*v.z + v.w*v.w;
#pragma unroll
    for (int o2 = 16; o2 > 0; o2 >>= 1) {
        s  += __shfl_xor_sync(0xffffffffu, s,  o2);
        s2 += __shfl_xor_sync(0xffffffffu, s2, o2);
    }
    if ((tid & 31) == 0) { sm[tid>>5] = s; sm2[tid>>5] = s2; }
    __syncthreads();
    float ts = 0.f, ts2 = 0.f;
#pragma unroll
    for (int w = 0; w < 8; w++) { ts += sm[w]; ts2 += sm2[w]; }
    const float mean = ts * (1.0f/Dq);
    const float var  = ts2 * (1.0f/Dq) - mean*mean;
    const float rstd = rsqrtf(var + 1e-6f);

    const float4 gg = reinterpret_cast<const float4*>(gamma)[tid];
    const float4 bb = reinterpret_cast<const float4*>(beta)[tid];
    float4 r;
    r.x = (v.x - mean) * rstd * gg.x + bb.x;
    r.y = (v.y - mean) * rstd * gg.y + bb.y;
    r.z = (v.z - mean) * rstd * gg.z + bb.z;
    r.w = (v.w - mean) * rstd * gg.w + bb.w;
    o[tid] = r;
}

// ============================================================
extern "C" void kernel_launch(void* const* d_in, const int* in_sizes, int n_in,
                              void* d_out, int out_size)
{
    const float* Q     = (const float*)d_in[0];
    const float* K     = (const float*)d_in[1];
    const float* V     = (const float*)d_in[2];
    const float* Wq    = (const float*)d_in[3];
    const float* bq    = (const float*)d_in[4];
    const float* Wk    = (const float*)d_in[5];
    const float* bk    = (const float*)d_in[6];
    const float* Wv    = (const float*)d_in[7];
    const float* bv    = (const float*)d_in[8];
    const float* Wo    = (const float*)d_in[9];
    const float* bo    = (const float*)d_in[10];
    const float* gamma = (const float*)d_in[11];
    const float* beta  = (const float*)d_in[12];

    float* out    = (float*)d_out;
    float* scores = out + OUT_OFF;

    float *gq, *gk, *gv, *gctx, *gy;
    cudaGetSymbolAddress((void**)&gq,   g_q);
    cudaGetSymbolAddress((void**)&gk,   g_k);
    cudaGetSymbolAddress((void**)&gv,   g_v);
    cudaGetSymbolAddress((void**)&gctx, g_ctx);
    cudaGetSymbolAddress((void**)&gy,   g_y);

    dim3 blk(256);

    // QKV projections: [4096,1024] x [1024,1024]^T
    dim3 gProj(Dq/128, Mq/128);               // (8, 32)
    proj_kernel<<<gProj, blk>>>(Q, Wq, bq, nullptr, gq);
    proj_kernel<<<gProj, blk>>>(K, Wk, bk, nullptr, gk);
    proj_kernel<<<gProj, blk>>>(V, Wv, bv, nullptr, gv);

    // logits -> scores region
    dim3 gSc(Sq/128, Sq/128, Bq*Hq);          // (16, 16, 32)
    scores_kernel<<<gSc, blk>>>(scores);

    // softmax rows
    softmax_kernel<<<(unsigned)((size_t)Bq*Hq*Sq), blk>>>(scores);

    // PV
    dim3 gAv(1, Sq/128, Bq*Hq);               // (1, 16, 32)
    av_kernel<<<gAv, blk>>>(scores);

    // O projection + bias + residual -> g_y
    proj_kernel<<<gProj, blk>>>(gctx, Wo, bo, Q, gy);

    // LayerNorm -> out region
    ln_kernel<<<(unsigned)Mq, blk>>>(gamma, beta, out);
}

// round 4
// speedup vs baseline: 3.0470x; 1.7424x over previous
#include <cuda_runtime.h>
#include <cuda_bf16.h>
#include <math.h>
#include <stdint.h>

#define Bq 2
#define Sq 2048
#define Dq 1024
#define Hq 16
#define DHq 64
#define Mq (Bq*Sq)
#define NELEM (Mq*Dq)
#define OUT_OFF ((size_t)Mq*Dq)

typedef __nv_bfloat16 bf16;
typedef __nv_bfloat162 bf162;

// ---------------- global scratch (no allocs allowed) ----------------
__device__ __align__(16) bf16 g_wh[4][Dq*Dq];
__device__ __align__(16) bf16 g_wl[4][Dq*Dq];
__device__ __align__(16) bf16 g_xh[3][NELEM];
__device__ __align__(16) bf16 g_xl[3][NELEM];
__device__ __align__(16) bf16 g_qh[NELEM], g_ql[NELEM];
__device__ __align__(16) bf16 g_kh[NELEM], g_kl[NELEM];
__device__ __align__(16) bf16 g_vh[NELEM], g_vl[NELEM];
__device__ __align__(16) bf16 g_ch[NELEM], g_cl[NELEM];
__device__ float g_y[NELEM];

// ---------------- helpers ----------------
__device__ __forceinline__ uint32_t s2u(const void* p){ return (uint32_t)__cvta_generic_to_shared(p); }
__device__ __forceinline__ void cpa16(uint32_t s, const void* g){
    asm volatile("cp.async.cg.shared.global [%0], [%1], 16;\n" :: "r"(s), "l"(g));
}
__device__ __forceinline__ void cpcommit(){ asm volatile("cp.async.commit_group;\n" ::: "memory"); }
__device__ __forceinline__ void cpwait(){ asm volatile("cp.async.wait_group 0;\n" ::: "memory"); }
__device__ __forceinline__ void ldm4(uint32_t a, uint32_t&r0,uint32_t&r1,uint32_t&r2,uint32_t&r3){
    asm volatile("ldmatrix.sync.aligned.m8n8.x4.shared.b16 {%0,%1,%2,%3}, [%4];\n"
        : "=r"(r0),"=r"(r1),"=r"(r2),"=r"(r3) : "r"(a));
}
__device__ __forceinline__ void ldm4t(uint32_t a, uint32_t&r0,uint32_t&r1,uint32_t&r2,uint32_t&r3){
    asm volatile("ldmatrix.sync.aligned.m8n8.x4.trans.shared.b16 {%0,%1,%2,%3}, [%4];\n"
        : "=r"(r0),"=r"(r1),"=r"(r2),"=r"(r3) : "r"(a));
}
__device__ __forceinline__ void mma16(float* c, uint32_t a0,uint32_t a1,uint32_t a2,uint32_t a3,
                                      uint32_t b0,uint32_t b1){
    asm volatile("mma.sync.aligned.m16n8k16.row.col.f32.bf16.bf16.f32 "
        "{%0,%1,%2,%3}, {%4,%5,%6,%7}, {%8,%9}, {%0,%1,%2,%3};\n"
        : "+f"(c[0]),"+f"(c[1]),"+f"(c[2]),"+f"(c[3])
        : "r"(a0),"r"(a1),"r"(a2),"r"(a3),"r"(b0),"r"(b1));
}
__device__ __forceinline__ void split2(float x, bf16& h, bf16& l){
    h = __float2bfloat16(x);
    l = __float2bfloat16(x - __bfloat162float(h));
}

// ---------------- prep: split f32 -> bf16 hi/lo ----------------
__global__ void split_kernel(const float* __restrict__ x, bf16* __restrict__ ho,
                             bf16* __restrict__ lo, int n4)
{
    int i = blockIdx.x*blockDim.x + threadIdx.x;
    if (i >= n4) return;
    float4 v = reinterpret_cast<const float4*>(x)[i];
    bf16 h0,l0,h1,l1,h2,l2,h3,l3;
    split2(v.x,h0,l0); split2(v.y,h1,l1); split2(v.z,h2,l2); split2(v.w,h3,l3);
    reinterpret_cast<bf162*>(ho)[2*i+0] = __halves2bfloat162(h0,h1);
    reinterpret_cast<bf162*>(ho)[2*i+1] = __halves2bfloat162(h2,h3);
    reinterpret_cast<bf162*>(lo)[2*i+0] = __halves2bfloat162(l0,l1);
    reinterpret_cast<bf162*>(lo)[2*i+1] = __halves2bfloat162(l2,l3);
}

// ============================================================
// Shared 128x128 GEMM core (NT): acc += A[128,K]*B[128,K]^T (bf16x3 split)
// 8 warps (64x32 warp tiles), BK=16, 2-stage cp.async pipeline.
// smem per stage: Ah(6144) Al(6144) Bh(6144) Bl(6144) = 24576; 2 stages = 48KB
// rows padded to 48B for conflict-free ldmatrix.
// ============================================================
template<int KT>
__device__ __forceinline__ void gemm_core(
    const bf16* __restrict__ Ahg, const bf16* __restrict__ Alg,
    const bf16* __restrict__ Bhg, const bf16* __restrict__ Blg,
    int bm, int bn, char* smem, float acc[4][4][4])
{
    const int tid = threadIdx.x;
    const int lane = tid & 31, warp = tid >> 5;
    const int wm = (warp>>2)*64, wn = (warp&3)*32;
    const uint32_t sb = s2u(smem);
    const int row = tid>>1, hf = tid&1;

    // prologue
    {
        uint32_t s0 = sb + (uint32_t)(row*48 + hf*16);
        size_t ga = (size_t)(bm+row)*Dq + hf*8;
        size_t gb = (size_t)(bn+row)*Dq + hf*8;
        cpa16(s0 + 0,     Ahg + ga);
        cpa16(s0 + 6144,  Alg + ga);
        cpa16(s0 + 12288, Bhg + gb);
        cpa16(s0 + 18432, Blg + gb);
        cpcommit();
    }

    for (int kt = 0; kt < KT; kt++){
        cpwait();
        __syncthreads();
        if (kt+1 < KT){
            uint32_t s0 = sb + (uint32_t)(((kt+1)&1)*24576 + row*48 + hf*16);
            const int k0 = (kt+1)*16;
            size_t ga = (size_t)(bm+row)*Dq + k0 + hf*8;
            size_t gb = (size_t)(bn+row)*Dq + k0 + hf*8;
            cpa16(s0 + 0,     Ahg + ga);
            cpa16(s0 + 6144,  Alg + ga);
            cpa16(s0 + 12288, Bhg + gb);
            cpa16(s0 + 18432, Blg + gb);
            cpcommit();
        }
        const uint32_t st = sb + (uint32_t)((kt&1)*24576);
        uint32_t bhf[4][2], blf[4][2];
#pragma unroll
        for (int p = 0; p < 2; p++){
            uint32_t addr = st + 12288u +
                (uint32_t)((wn + p*16 + (lane&7) + ((lane>>4)&1)*8)*48 + ((lane>>3)&1)*16);
            ldm4(addr,        bhf[2*p][0], bhf[2*p][1], bhf[2*p+1][0], bhf[2*p+1][1]);
            ldm4(addr + 6144, blf[2*p][0], blf[2*p][1], blf[2*p+1][0], blf[2*p+1][1]);
        }
#pragma unroll
        for (int mi = 0; mi < 4; mi++){
            uint32_t aaddr = st + (uint32_t)((wm + mi*16 + (lane&15))*48 + ((lane>>4)&1)*16);
            uint32_t a0,a1,a2,a3, l0,l1,l2,l3;
            ldm4(aaddr,        a0,a1,a2,a3);
            ldm4(aaddr + 6144, l0,l1,l2,l3);
#pragma unroll
            for (int ni = 0; ni < 4; ni++){
                mma16(acc[mi][ni], a0,a1,a2,a3, bhf[ni][0], bhf[ni][1]);
                mma16(acc[mi][ni], a0,a1,a2,a3, blf[ni][0], blf[ni][1]);
                mma16(acc[mi][ni], l0,l1,l2,l3, bhf[ni][0], bhf[ni][1]);
            }
        }
    }
}

// ============================================================
// Projection: C = A*W^T + bias (+resid). Split-out (q/k/v) or f32-out (O).
// ============================================================
__global__ __launch_bounds__(256,2) void proj_kernel(
    const bf16* __restrict__ Ahg, const bf16* __restrict__ Alg,
    const bf16* __restrict__ Bhg, const bf16* __restrict__ Blg,
    const float* __restrict__ bias, const float* __restrict__ resid,
    bf16* __restrict__ outh, bf16* __restrict__ outl, float* __restrict__ outf)
{
    __shared__ char smem[49152];
    float acc[4][4][4] = {};
    const int bm = blockIdx.y*128, bn = blockIdx.x*128;
    gemm_core<64>(Ahg,Alg,Bhg,Blg,bm,bn,smem,acc);

    const int lane = threadIdx.x & 31, warp = threadIdx.x>>5;
    const int wm=(warp>>2)*64, wn=(warp&3)*32, g=lane>>2, tg=lane&3;
#pragma unroll
    for (int mi=0; mi<4; mi++)
#pragma unroll
    for (int ni=0; ni<4; ni++){
        const int r0 = bm+wm+mi*16+g;
        const int c  = bn+wn+ni*8+tg*2;
        const float2 bv = *reinterpret_cast<const float2*>(&bias[c]);
        const float x0=acc[mi][ni][0]+bv.x, x1=acc[mi][ni][1]+bv.y;
        const float x2=acc[mi][ni][2]+bv.x, x3=acc[mi][ni][3]+bv.y;
        if (outf){
            const float2 q0 = *reinterpret_cast<const float2*>(&resid[(size_t)r0*Dq + c]);
            const float2 q1 = *reinterpret_cast<const float2*>(&resid[(size_t)(r0+8)*Dq + c]);
            *reinterpret_cast<float2*>(&outf[(size_t)r0*Dq+c])     = make_float2(x0+q0.x, x1+q0.y);
            *reinterpret_cast<float2*>(&outf[(size_t)(r0+8)*Dq+c]) = make_float2(x2+q1.x, x3+q1.y);
        } else {
            bf16 h0,l0,h1,l1;
            split2(x0,h0,l0); split2(x1,h1,l1);
            *reinterpret_cast<bf162*>(&outh[(size_t)r0*Dq+c]) = __halves2bfloat162(h0,h1);
            *reinterpret_cast<bf162*>(&outl[(size_t)r0*Dq+c]) = __halves2bfloat162(l0,l1);
            split2(x2,h0,l0); split2(x3,h1,l1);
            *reinterpret_cast<bf162*>(&outh[(size_t)(r0+8)*Dq+c]) = __halves2bfloat162(h0,h1);
            *reinterpret_cast<bf162*>(&outl[(size_t)(r0+8)*Dq+c]) = __halves2bfloat162(l0,l1);
        }
    }
}

// ============================================================
// Scores: per (b,h) P[q,k] = (q . k) / 8
// ============================================================
__global__ __launch_bounds__(256,2) void scores_kernel(float* __restrict__ scores)
{
    __shared__ char smem[49152];
    const int bh = blockIdx.z, b = bh>>4, h = bh&15;
    const size_t boff = (size_t)b*Sq*Dq + h*DHq;
    float acc[4][4][4] = {};
    const int bm = blockIdx.y*128, bn = blockIdx.x*128;
    gemm_core<4>(g_qh+boff, g_ql+boff, g_kh+boff, g_kl+boff, bm, bn, smem, acc);

    float* C = scores + (size_t)bh*Sq*Sq;
    const int lane = threadIdx.x & 31, warp = threadIdx.x>>5;
    const int wm=(warp>>2)*64, wn=(warp&3)*32, g=lane>>2, tg=lane&3;
#pragma unroll
    for (int mi=0; mi<4; mi++)
#pragma unroll
    for (int ni=0; ni<4; ni++){
        const int r0 = bm+wm+mi*16+g;
        const int c  = bn+wn+ni*8+tg*2;
        *reinterpret_cast<float2*>(&C[(size_t)r0*Sq+c]) =
            make_float2(acc[mi][ni][0]*0.125f, acc[mi][ni][1]*0.125f);
        *reinterpret_cast<float2*>(&C[(size_t)(r0+8)*Sq+c]) =
            make_float2(acc[mi][ni][2]*0.125f, acc[mi][ni][3]*0.125f);
    }
}

// ============================================================
// Softmax rows (in place), 2048 per row
// ============================================================
__global__ void softmax_kernel(float* __restrict__ scores)
{
    const size_t row = blockIdx.x;
    float4* p = reinterpret_cast<float4*>(scores + row * (size_t)Sq);
    const int tid = threadIdx.x;
    __shared__ float sm[8];

    float4 v[2];
    float lmax = -INFINITY;
#pragma unroll
    for (int t = 0; t < 2; t++) {
        v[t] = p[tid + t*256];
        lmax = fmaxf(lmax, fmaxf(fmaxf(v[t].x, v[t].y), fmaxf(v[t].z, v[t].w)));
    }
#pragma unroll
    for (int o = 16; o > 0; o >>= 1)
        lmax = fmaxf(lmax, __shfl_xor_sync(0xffffffffu, lmax, o));
    if ((tid & 31) == 0) sm[tid >> 5] = lmax;
    __syncthreads();
    float rmax = sm[0];
#pragma unroll
    for (int w = 1; w < 8; w++) rmax = fmaxf(rmax, sm[w]);
    __syncthreads();

    float lsum = 0.f;
#pragma unroll
    for (int t = 0; t < 2; t++) {
        v[t].x = expf(v[t].x - rmax); v[t].y = expf(v[t].y - rmax);
        v[t].z = expf(v[t].z - rmax); v[t].w = expf(v[t].w - rmax);
        lsum += v[t].x + v[t].y + v[t].z + v[t].w;
    }
#pragma unroll
    for (int o = 16; o > 0; o >>= 1)
        lsum += __shfl_xor_sync(0xffffffffu, lsum, o);
    if ((tid & 31) == 0) sm[tid >> 5] = lsum;
    __syncthreads();
    float rsum = 0.f;
#pragma unroll
    for (int w = 0; w < 8; w++) rsum += sm[w];
    const float inv = 1.0f / rsum;
#pragma unroll
    for (int t = 0; t < 2; t++) {
        v[t].x *= inv; v[t].y *= inv; v[t].z *= inv; v[t].w *= inv;
        p[tid + t*256] = v[t];
    }
}

// ============================================================
// PV: ctx[q, h*64+d] = sum_k P[q,k]*V[k, h*64+d]  (split bf16 out)
// 128x64 block, 8 warps (32x32 warp tiles), BK=16, 2-stage pipeline.
// smem/stage: Ph(6144) Pl(6144) Vh(2304) Vl(2304) = 16896; x2 = 33792B
// ============================================================
__global__ __launch_bounds__(256,2) void av_kernel(const float* __restrict__ scores)
{
    __shared__ char smem[2*16896];
    const int bh = blockIdx.z, b = bh>>4, h = bh&15;
    const float* P = scores + (size_t)bh*Sq*Sq;
    const bf16* Vhg = g_vh + (size_t)b*Sq*Dq + h*DHq;
    const bf16* Vlg = g_vl + (size_t)b*Sq*Dq + h*DHq;
    const int tid = threadIdx.x, lane = tid&31, warp = tid>>5;
    const int wm = (warp>>1)*32, wn = (warp&1)*32;
    const int bm = blockIdx.y*128;
    const uint32_t sb = s2u(smem);

    float acc[2][4][4] = {};

    // V cp.async mapping
    const int va = tid>>7, vr = (tid>>3)&15, vc = tid&7;
    const bf16* vsrc = va ? Vlg : Vhg;

    // P LDG mapping: chunks tid (rows 0-63) and tid+256 (rows 64-127)
    const int pr = tid>>2, pq = (tid&3)*4;

    float4 p0, p1, n0, n1;
    p0 = *reinterpret_cast<const float4*>(&P[(size_t)(bm + pr)*Sq + pq]);
    p1 = *reinterpret_cast<const float4*>(&P[(size_t)(bm + 64 + pr)*Sq + pq]);
    {
        uint32_t s = sb + 12288u + (uint32_t)(va*2304 + vr*144 + vc*16);
        cpa16(s, vsrc + (size_t)vr*Dq + vc*8);
        cpcommit();
    }

    for (int kt = 0; kt < 128; kt++){
        const int s = kt&1;
        const uint32_t st = sb + (uint32_t)(s*16896);
        // store P (split) into stage s
        {
            bf16 h0,l0,h1,l1,h2,l2,h3,l3;
            char* base = smem + s*16896;
            split2(p0.x,h0,l0); split2(p0.y,h1,l1); split2(p0.z,h2,l2); split2(p0.w,h3,l3);
            *reinterpret_cast<bf162*>(base + pr*48 + pq*2)          = __halves2bfloat162(h0,h1);
            *reinterpret_cast<bf162*>(base + pr*48 + pq*2 + 4)      = __halves2bfloat162(h2,h3);
            *reinterpret_cast<bf162*>(base + 6144 + pr*48 + pq*2)   = __halves2bfloat162(l0,l1);
            *reinterpret_cast<bf162*>(base + 6144 + pr*48 + pq*2+4) = __halves2bfloat162(l2,l3);
            split2(p1.x,h0,l0); split2(p1.y,h1,l1); split2(p1.z,h2,l2); split2(p1.w,h3,l3);
            *reinterpret_cast<bf162*>(base + (pr+64)*48 + pq*2)          = __halves2bfloat162(h0,h1);
            *reinterpret_cast<bf162*>(base + (pr+64)*48 + pq*2 + 4)      = __halves2bfloat162(h2,h3);
            *reinterpret_cast<bf162*>(base + 6144 + (pr+64)*48 + pq*2)   = __halves2bfloat162(l0,l1);
            *reinterpret_cast<bf162*>(base + 6144 + (pr+64)*48 + pq*2+4) = __halves2bfloat162(l2,l3);
        }
        if (kt+1 < 128){
            const int k0 = (kt+1)*16;
            n0 = *reinterpret_cast<const float4*>(&P[(size_t)(bm + pr)*Sq + k0 + pq]);
            n1 = *reinterpret_cast<const float4*>(&P[(size_t)(bm + 64 + pr)*Sq + k0 + pq]);
        }
        cpwait();
        __syncthreads();
        if (kt+1 < 128){
            const int k0 = (kt+1)*16;
            uint32_t sv = sb + (uint32_t)((s^1)*16896) + 12288u + (uint32_t)(va*2304 + vr*144 + vc*16);
            cpa16(sv, vsrc + (size_t)(k0+vr)*Dq + vc*8);
            cpcommit();
        }
        // compute
        uint32_t bhf[4][2], blf[4][2];
#pragma unroll
        for (int p = 0; p < 2; p++){
            uint32_t addr = st + 12288u +
                (uint32_t)(((lane>>3)&1)*8*144 + (lane&7)*144 + (wn + p*16 + ((lane>>4)&1)*8)*2);
            ldm4t(addr,        bhf[2*p][0], bhf[2*p][1], bhf[2*p+1][0], bhf[2*p+1][1]);
            ldm4t(addr + 2304, blf[2*p][0], blf[2*p][1], blf[2*p+1][0], blf[2*p+1][1]);
        }
#pragma unroll
        for (int mi = 0; mi < 2; mi++){
            uint32_t aaddr = st + (uint32_t)((wm + mi*16 + (lane&15))*48 + ((lane>>4)&1)*16);
            uint32_t a0,a1,a2,a3, l0,l1,l2,l3;
            ldm4(aaddr,        a0,a1,a2,a3);
            ldm4(aaddr + 6144, l0,l1,l2,l3);
#pragma unroll
            for (int ni = 0; ni < 4; ni++){
                mma16(acc[mi][ni], a0,a1,a2,a3, bhf[ni][0], bhf[ni][1]);
                mma16(acc[mi][ni], a0,a1,a2,a3, blf[ni][0], blf[ni][1]);
                mma16(acc[mi][ni], l0,l1,l2,l3, bhf[ni][0], bhf[ni][1]);
            }
        }
        p0 = n0; p1 = n1;
    }

    const int g = lane>>2, tg = lane&3;
#pragma unroll
    for (int mi = 0; mi < 2; mi++)
#pragma unroll
    for (int ni = 0; ni < 4; ni++){
        const int r0 = bm + wm + mi*16 + g;
        const int c  = wn + ni*8 + tg*2;
        const size_t i0 = (size_t)(b*Sq + r0)*Dq + h*DHq + c;
        const size_t i1 = (size_t)(b*Sq + r0 + 8)*Dq + h*DHq + c;
        bf16 h0,l0,h1,l1;
        split2(acc[mi][ni][0],h0,l0); split2(acc[mi][ni][1],h1,l1);
        *reinterpret_cast<bf162*>(&g_ch[i0]) = __halves2bfloat162(h0,h1);
        *reinterpret_cast<bf162*>(&g_cl[i0]) = __halves2bfloat162(l0,l1);
        split2(acc[mi][ni][2],h0,l0); split2(acc[mi][ni][3],h1,l1);
        *reinterpret_cast<bf162*>(&g_ch[i1]) = __halves2bfloat162(h0,h1);
        *reinterpret_cast<bf162*>(&g_cl[i1]) = __halves2bfloat162(l0,l1);
    }
}

// ============================================================
// LayerNorm per row of g_y -> d_out
// ============================================================
__global__ void ln_kernel(const float* __restrict__ gamma,
                          const float* __restrict__ beta,
                          float* __restrict__ out)
{
    const size_t row = blockIdx.x;
    const float4* y = reinterpret_cast<const float4*>(g_y + row * (size_t)Dq);
    float4* o = reinterpret_cast<float4*>(out + row * (size_t)Dq);
    const int tid = threadIdx.x;
    __shared__ float sm[8], sm2[8];

    float4 v = y[tid];
    float s  = v.x + v.y + v.z + v.w;
    float s2 = v.x*v.x + v.y*v.y + v.z*v.z + v.w*v.w;
#pragma unroll
    for (int o2 = 16; o2 > 0; o2 >>= 1) {
        s  += __shfl_xor_sync(0xffffffffu, s,  o2);
        s2 += __shfl_xor_sync(0xffffffffu, s2, o2);
    }
    if ((tid & 31) == 0) { sm[tid>>5] = s; sm2[tid>>5] = s2; }
    __syncthreads();
    float ts = 0.f, ts2 = 0.f;
#pragma unroll
    for (int w = 0; w < 8; w++) { ts += sm[w]; ts2 += sm2[w]; }
    const float mean = ts * (1.0f/Dq);
    const float var  = ts2 * (1.0f/Dq) - mean*mean;
    const float rstd = rsqrtf(var + 1e-6f);

    const float4 gg = reinterpret_cast<const float4*>(gamma)[tid];
    const float4 bb = reinterpret_cast<const float4*>(beta)[tid];
    float4 r;
    r.x = (v.x - mean) * rstd * gg.x + bb.x;
    r.y = (v.y - mean) * rstd * gg.y + bb.y;
    r.z = (v.z - mean) * rstd * gg.z + bb.z;
    r.w = (v.w - mean) * rstd * gg.w + bb.w;
    o[tid] = r;
}

// ============================================================
extern "C" void kernel_launch(void* const* d_in, const int* in_sizes, int n_in,
                              void* d_out, int out_size)
{
    const float* Q     = (const float*)d_in[0];
    const float* K     = (const float*)d_in[1];
    const float* V     = (const float*)d_in[2];
    const float* Wq    = (const float*)d_in[3];
    const float* bq    = (const float*)d_in[4];
    const float* Wk    = (const float*)d_in[5];
    const float* bk    = (const float*)d_in[6];
    const float* Wv    = (const float*)d_in[7];
    const float* bv    = (const float*)d_in[8];
    const float* Wo    = (const float*)d_in[9];
    const float* bo    = (const float*)d_in[10];
    const float* gamma = (const float*)d_in[11];
    const float* beta  = (const float*)d_in[12];

    float* out    = (float*)d_out;
    float* scores = out + OUT_OFF;

    bf16 *wh, *wl, *xh, *xl, *qh, *ql, *kh, *kl, *vh, *vl, *ch, *cl;
    float* gy;
    cudaGetSymbolAddress((void**)&wh, g_wh);
    cudaGetSymbolAddress((void**)&wl, g_wl);
    cudaGetSymbolAddress((void**)&xh, g_xh);
    cudaGetSymbolAddress((void**)&xl, g_xl);
    cudaGetSymbolAddress((void**)&qh, g_qh); cudaGetSymbolAddress((void**)&ql, g_ql);
    cudaGetSymbolAddress((void**)&kh, g_kh); cudaGetSymbolAddress((void**)&kl, g_kl);
    cudaGetSymbolAddress((void**)&vh, g_vh); cudaGetSymbolAddress((void**)&vl, g_vl);
    cudaGetSymbolAddress((void**)&ch, g_ch); cudaGetSymbolAddress((void**)&cl, g_cl);
    cudaGetSymbolAddress((void**)&gy, g_y);

    const int WN = Dq*Dq;     // 1M elems per weight

    // prep splits
    split_kernel<<<WN/4/256, 256>>>(Wq, wh + 0*WN, wl + 0*WN, WN/4);
    split_kernel<<<WN/4/256, 256>>>(Wk, wh + 1*WN, wl + 1*WN, WN/4);
    split_kernel<<<WN/4/256, 256>>>(Wv, wh + 2*WN, wl + 2*WN, WN/4);
    split_kernel<<<WN/4/256, 256>>>(Wo, wh + 3*WN, wl + 3*WN, WN/4);
    split_kernel<<<NELEM/4/256, 256>>>(Q, xh + 0*(size_t)NELEM, xl + 0*(size_t)NELEM, NELEM/4);
    split_kernel<<<NELEM/4/256, 256>>>(K, xh + 1*(size_t)NELEM, xl + 1*(size_t)NELEM, NELEM/4);
    split_kernel<<<NELEM/4/256, 256>>>(V, xh + 2*(size_t)NELEM, xl + 2*(size_t)NELEM, NELEM/4);

    dim3 blk(256);
    dim3 gProj(Dq/128, Mq/128);     // (8, 32)
    proj_kernel<<<gProj, blk>>>(xh+0*(size_t)NELEM, xl+0*(size_t)NELEM, wh+0*WN, wl+0*WN,
                                bq, nullptr, qh, ql, nullptr);
    proj_kernel<<<gProj, blk>>>(xh+1*(size_t)NELEM, xl+1*(size_t)NELEM, wh+1*WN, wl+1*WN,
                                bk, nullptr, kh, kl, nullptr);
    proj_kernel<<<gProj, blk>>>(xh+2*(size_t)NELEM, xl+2*(size_t)NELEM, wh+2*WN, wl+2*WN,
                                bv, nullptr, vh, vl, nullptr);

    dim3 gSc(Sq/128, Sq/128, Bq*Hq);   // (16,16,32)
    scores_kernel<<<gSc, blk>>>(scores);

    softmax_kernel<<<(unsigned)((size_t)Bq*Hq*Sq), blk>>>(scores);

    dim3 gAv(1, Sq/128, Bq*Hq);        // (1,16,32)
    av_kernel<<<gAv, blk>>>(scores);

    proj_kernel<<<gProj, blk>>>(ch, cl, wh+3*WN, wl+3*WN, bo, Q, nullptr, nullptr, gy);

    ln_kernel<<<(unsigned)Mq, blk>>>(gamma, beta, out);
}